// round 15
// baseline (speedup 1.0000x reference)
#include <cuda_runtime.h>
#include <math.h>

#define BS 2
#define NPTS 8192
#define C3D 64
#define HH 64
#define WW 160
#define HW (HH*WW)
#define KNN 3

#define CW 80          // cells in x (2px each)
#define CHC 32         // cells in y
#define NCELL (CW*CHC)
#define NTOT (BS*NCELL)

#define NCAND 576      // smem candidate cap (expected ~320 for 5 rows)

#define FLT_BIG 3.402823466e+38f

// ---------------- scratch ----------------
__device__ float4 g_pts[BS * NPTS];        // (x, y, s2_replica, 0) by original index
__device__ int    g_cnt[NTOT];             // zero-init; re-zeroed by fused kernel each run
__device__ int    g_rowstart[NTOT + 1];
__device__ int    g_off[NTOT];
__device__ float4 g_cpts[BS * NPTS];       // CSR-compacted (x, y, s2, idx_bits)
__device__ float  g_f3dT[BS * NPTS * C3D]; // point-major feat_3d

__device__ __forceinline__ int cell_of(float ux, float uy, int b) {
    int cx = (int)(ux * 0.5f); cx = max(0, min(CW - 1, cx));
    int cy = (int)(uy * 0.5f); cy = max(0, min(CHC - 1, cy));
    return (b * CHC + cy) * CW + cx;
}

// ---------------- K1: transpose feat_3d (vectorized) + pack/count ----------
__global__ void __launch_bounds__(256) prep_kernel(const float* __restrict__ uv,
                                                   const float* __restrict__ f3d) {
    const int t = threadIdx.x;
    if (blockIdx.x < 1024) {
        __shared__ float tile[32][33];
        const int bid = blockIdx.x;
        const int b  = bid >> 9;
        const int c0 = ((bid >> 8) & 1) * 32;
        const int n0 = (bid & 255) * 32;
        const int tx2 = t & 7;
        const int row = t >> 3;
        float4 v = *reinterpret_cast<const float4*>(
            f3d + ((size_t)(b * C3D + c0 + row)) * NPTS + n0 + tx2 * 4);
        tile[row][tx2 * 4 + 0] = v.x;
        tile[row][tx2 * 4 + 1] = v.y;
        tile[row][tx2 * 4 + 2] = v.z;
        tile[row][tx2 * 4 + 3] = v.w;
        __syncthreads();
        const int n = t >> 3;
        float4 o;
        o.x = tile[tx2 * 4 + 0][n];
        o.y = tile[tx2 * 4 + 1][n];
        o.z = tile[tx2 * 4 + 2][n];
        o.w = tile[tx2 * 4 + 3][n];
        *reinterpret_cast<float4*>(
            g_f3dT + ((size_t)(b * NPTS + n0 + n)) * C3D + c0 + tx2 * 4) = o;
    } else {
        const int i = (blockIdx.x - 1024) * 256 + t;
        const int b = i >> 13;
        const int n = i & (NPTS - 1);
        const float ux = uv[(b * 2 + 0) * NPTS + n];
        const float uy = uv[(b * 2 + 1) * NPTS + n];
        const float s2 = __fadd_rn(__fmul_rn(ux, ux), __fmul_rn(uy, uy));
        g_pts[i] = make_float4(ux, uy, s2, 0.0f);
        atomicAdd(&g_cnt[cell_of(ux, uy, b)], 1);
    }
}

// ---------------- K2: exclusive scan over NTOT=5120 cells (one block) ----------
__global__ void __launch_bounds__(1024) scan_kernel() {
    const int t = threadIdx.x;
    int c[5], s = 0;
    #pragma unroll
    for (int k = 0; k < 5; ++k) { c[k] = g_cnt[t * 5 + k]; s += c[k]; }
    const int lane = t & 31, w = t >> 5;
    int v = s;
    #pragma unroll
    for (int o = 1; o < 32; o <<= 1) {
        int u = __shfl_up_sync(0xffffffffu, v, o);
        if (lane >= o) v += u;
    }
    __shared__ int ws[32];
    if (lane == 31) ws[w] = v;
    __syncthreads();
    if (w == 0) {
        int x = ws[lane];
        #pragma unroll
        for (int o = 1; o < 32; o <<= 1) {
            int u = __shfl_up_sync(0xffffffffu, x, o);
            if (lane >= o) x += u;
        }
        ws[lane] = x;
    }
    __syncthreads();
    int run = v - s + (w > 0 ? ws[w - 1] : 0);
    #pragma unroll
    for (int k = 0; k < 5; ++k) {
        g_rowstart[t * 5 + k] = run;
        g_off[t * 5 + k] = run;
        run += c[k];
    }
    if (t == 1023) g_rowstart[NTOT] = run;
}

// ---------------- K3: scatter into CSR ----------------
__global__ void __launch_bounds__(256) scatter_kernel() {
    const int i = blockIdx.x * 256 + threadIdx.x;
    const int b = i >> 13;
    const int n = i & (NPTS - 1);
    const float4 p = g_pts[i];
    const int slot = atomicAdd(&g_off[cell_of(p.x, p.y, b)], 1);
    g_cpts[slot] = make_float4(p.x, p.y, p.z, __int_as_float(n));
}

// ---------------- helpers ----------------
__device__ __forceinline__ bool lessMI(float ma, int ia, float mb, int ib) {
    return (ma < mb) || (ma == mb && ia < ib);
}
__device__ __forceinline__ void ins(float d, int id,
                                    float& d0, float& d1, float& d2v,
                                    int& j0, int& j1, int& j2) {
    if (lessMI(d, id, d2v, j2)) {
        if (lessMI(d, id, d1, j1)) {
            d2v = d1; j2 = j1;
            if (lessMI(d, id, d0, j0)) { d1 = d0; j1 = j0; d0 = d; j0 = id; }
            else                       { d1 = d;  j1 = id; }
        } else { d2v = d; j2 = id; }
    }
}
// Dedup insert for merges: skips (d,id) already present (ids are unique per point).
__device__ __forceinline__ void ins_dedup(float d, int id,
                                          float& d0, float& d1, float& d2v,
                                          int& j0, int& j1, int& j2) {
    if (id == j0 || id == j1 || id == j2) return;
    ins(d, id, d0, d1, d2v, j0, j1, j2);
}
__device__ __forceinline__ void eval_pt(const float4 p, float qxf, float qyf, float s1,
                                        float& d0, float& d1, float& d2v,
                                        int& j0, int& j1, int& j2) {
    const float dot = __fmaf_rn(qyf, p.y, __fmul_rn(qxf, p.x));
    const float d2  = __fsub_rn(__fadd_rn(s1, p.z), __fmul_rn(2.0f, dot));
    ins(d2, __float_as_int(p.w), d0, d1, d2v, j0, j1, j2);
}
__device__ __forceinline__ void scan_span(int st, int en, int stride,
                                          float qxf, float qyf, float s1,
                                          float& d0, float& d1, float& d2v,
                                          int& j0, int& j1, int& j2) {
    for (int s = st; s < en; s += stride)
        eval_pt(__ldg(&g_cpts[s]), qxf, qyf, s1, d0, d1, d2v, j0, j1, j2);
}
__device__ __forceinline__ void row_bounds(int b, int cy, int cxlo, int cxhi,
                                           int& st, int& en) {
    st = 0; en = 0;
    if (cy < 0 || cy >= CHC) return;
    cxlo = max(cxlo, 0); cxhi = min(cxhi, CW - 1);
    if (cxlo > cxhi) return;
    const int rowbase = (b * CHC + cy) * CW;
    st = g_rowstart[rowbase + cxlo];
    en = g_rowstart[rowbase + cxhi + 1];
}

// ---------------- K4: fused, warp-private A->B1->B2 (pipelined), GEMM C ----------
// block = 32x2 pixel tile (64 queries), 256 threads. grid (5, 32, BS).
__global__ void __launch_bounds__(256) fused_kernel(
    const float* __restrict__ w1, const float* __restrict__ b1,
    const float* __restrict__ w2, const float* __restrict__ b2,
    const float* __restrict__ w3, const float* __restrict__ b3,
    float* __restrict__ out) {

    __shared__ float  s_w3[64 * 68];   // [j*68 + o] = w3[o][j]
    __shared__ float  s_buf[64 * 68];  // union: s_H (warp-private) then s_fin [j*68+lq]
    __shared__ float4 s_cand[NCAND];   // staged candidate points (5 cell rows)
    __shared__ int    s_rs[5][21];     // absolute rowstart boundaries per cell-row
    __shared__ int    s_st[5], s_cnt[5];
    __shared__ float  s_w1[48];
    __shared__ float  s_b1[16];

    float* const s_H   = s_buf;        // [ (wib*24 + l) * 20 + j ], l = 0..23
    float* const s_fin = s_buf;        // [ j*68 + lq ], live after all B2 reads

    const int t    = threadIdx.x;
    const int lane = t & 31;
    const int wib  = t >> 5;
    const int b    = blockIdx.z;
    const int X0   = blockIdx.x * 32;
    const int Y0   = blockIdx.y * 2;

    const int cyc  = Y0 >> 1;
    const int cxlo = max(X0 / 2 - 2, 0);
    const int cxhi = min(X0 / 2 + 17, CW - 1);

    // reset cell counters for next invocation (consumed earlier this run by scan)
    const int gtid = ((blockIdx.z * gridDim.y + blockIdx.y) * gridDim.x + blockIdx.x) * 256 + t;
    if (gtid < NTOT) g_cnt[gtid] = 0;

    if (t < 48) s_w1[t] = w1[t];
    if (t < 16) s_b1[t] = b1[t];

    // row bounds + boundary table for 5 cell rows (cyc-2 .. cyc+2)
    if (t < 5) {
        const int row = cyc - 2 + t;
        int st = 0, en = 0;
        if (row >= 0 && row < CHC) {
            const int rowbase = (b * CHC + row) * CW;
            st = g_rowstart[rowbase + cxlo];
            en = g_rowstart[rowbase + cxhi + 1];
        }
        s_st[t] = st; s_cnt[t] = en - st;
    }
    if (t < 105) {
        const int r = t / 21, c = t % 21;
        const int row = cyc - 2 + r;
        if (row >= 0 && row < CHC && c <= cxhi + 1 - cxlo)
            s_rs[r][c] = g_rowstart[(b * CHC + row) * CW + cxlo + c];
    }
    __syncthreads();

    int base_[5];
    base_[0] = 0;
    #pragma unroll
    for (int r = 1; r < 5; ++r) base_[r] = base_[r - 1] + s_cnt[r - 1];
    const int total_cand = base_[4] + s_cnt[4];
    const bool ovf = total_cand > NCAND;

    if (!ovf) {
        #pragma unroll
        for (int r = 0; r < 5; ++r) {
            const int cr = s_cnt[r], sr = s_st[r], br = base_[r];
            for (int i = t; i < cr; i += 256) s_cand[br + i] = __ldg(&g_cpts[sr + i]);
        }
    }

    // stage w3 transposed (coalesced gmem reads) — overlaps candidate copy
    for (int e = t; e < 64 * 64; e += 256) {
        int o = e >> 6, j = e & 63;
        s_w3[j * 68 + o] = w3[e];
    }
    __syncthreads();

    // ---- phase A: knn, 4 lanes per query, 3x3 fast path from smem ----
    const int sub = lane & 3;
    const int qq0 = lane >> 2;               // 0..7
    const int lq  = wib * 8 + qq0;           // 0..63
    const int qx  = X0 + (lq & 31);
    const int qy  = Y0 + (lq >> 5);
    const float qxf = (float)qx;
    const float qyf = (float)qy;
    const float s1  = __fadd_rn(__fmul_rn(qxf, qxf), __fmul_rn(qyf, qyf));
    const int qcx = qx >> 1;

    float d0 = FLT_BIG, d1 = FLT_BIG, d2v = FLT_BIG;
    int   j0 = 0x7fffffff, j1 = 0x7fffffff, j2 = 0x7fffffff;

    auto scan_cells_smem = [&](int ri, int clo, int chi) {
        const int row = cyc - 2 + ri;
        if (row < 0 || row >= CHC) return;
        clo = max(clo, cxlo); chi = min(chi, cxhi);
        if (clo > chi) return;
        const int lo_i = clo - cxlo, hi_i = chi - cxlo;
        const int ss = s_rs[ri][lo_i]     - s_st[ri] + base_[ri];
        const int ee = s_rs[ri][hi_i + 1] - s_st[ri] + base_[ri];
        for (int s = ss + sub; s < ee; s += 4)
            eval_pt(s_cand[s], qxf, qyf, s1, d0, d1, d2v, j0, j1, j2);
    };
    auto merge4 = [&]() {
        #pragma unroll
        for (int m = 1; m <= 2; m <<= 1) {
            float od0 = __shfl_xor_sync(0xffffffffu, d0,  m);
            float od1 = __shfl_xor_sync(0xffffffffu, d1,  m);
            float od2 = __shfl_xor_sync(0xffffffffu, d2v, m);
            int   oj0 = __shfl_xor_sync(0xffffffffu, j0,  m);
            int   oj1 = __shfl_xor_sync(0xffffffffu, j1,  m);
            int   oj2 = __shfl_xor_sync(0xffffffffu, j2,  m);
            ins_dedup(od0, oj0, d0, d1, d2v, j0, j1, j2);
            ins_dedup(od1, oj1, d0, d1, d2v, j0, j1, j2);
            ins_dedup(od2, oj2, d0, d1, d2v, j0, j1, j2);
        }
    };

    if (!ovf) {
        #pragma unroll
        for (int ri = 1; ri <= 3; ++ri)
            scan_cells_smem(ri, qcx - 1, qcx + 1);
        merge4();
        {
            const bool need = (d2v + 0.5f >= 4.0f);
            if (__any_sync(0xffffffffu, need)) {
                if (need) {
                    scan_cells_smem(0, qcx - 2, qcx + 2);
                    scan_cells_smem(4, qcx - 2, qcx + 2);
                    #pragma unroll
                    for (int ri = 1; ri <= 3; ++ri) {
                        scan_cells_smem(ri, qcx - 2, qcx - 2);
                        scan_cells_smem(ri, qcx + 2, qcx + 2);
                    }
                }
                merge4();
            }
        }
        if (sub == 0 && d2v + 0.5f >= 16.0f) {
            // tier-2 (P ~ 1e-14): exact serial gmem rings beyond the 5x5
            for (int r = 3; r < 96; ++r) {
                const float lb = 2.0f * (float)(r - 1);
                if (lb * lb > d2v + 0.5f) break;
                int st, en;
                row_bounds(b, cyc - r, qcx - r, qcx + r, st, en);
                scan_span(st, en, 1, qxf, qyf, s1, d0, d1, d2v, j0, j1, j2);
                row_bounds(b, cyc + r, qcx - r, qcx + r, st, en);
                scan_span(st, en, 1, qxf, qyf, s1, d0, d1, d2v, j0, j1, j2);
                for (int dy = -r + 1; dy <= r - 1; ++dy) {
                    row_bounds(b, cyc + dy, qcx - r, qcx - r, st, en);
                    scan_span(st, en, 1, qxf, qyf, s1, d0, d1, d2v, j0, j1, j2);
                    row_bounds(b, cyc + dy, qcx + r, qcx + r, st, en);
                    scan_span(st, en, 1, qxf, qyf, s1, d0, d1, d2v, j0, j1, j2);
                }
            }
        }
    } else {
        // overflow path (statistically never): same candidate sets from gmem
        #pragma unroll
        for (int dy = -1; dy <= 1; ++dy) {
            int st, en;
            row_bounds(b, cyc + dy, qcx - 1, qcx + 1, st, en);
            scan_span(st + sub, en, 4, qxf, qyf, s1, d0, d1, d2v, j0, j1, j2);
        }
        merge4();
        if (sub == 0 && d2v + 0.5f >= 4.0f) {
            for (int r = 2; r < 96; ++r) {
                const float lb = 2.0f * (float)(r - 1);
                if (lb * lb > d2v + 0.5f) break;
                int st, en;
                row_bounds(b, cyc - r, qcx - r, qcx + r, st, en);
                scan_span(st, en, 1, qxf, qyf, s1, d0, d1, d2v, j0, j1, j2);
                row_bounds(b, cyc + r, qcx - r, qcx + r, st, en);
                scan_span(st, en, 1, qxf, qyf, s1, d0, d1, d2v, j0, j1, j2);
                for (int dy = -r + 1; dy <= r - 1; ++dy) {
                    row_bounds(b, cyc + dy, qcx - r, qcx - r, st, en);
                    scan_span(st, en, 1, qxf, qyf, s1, d0, d1, d2v, j0, j1, j2);
                    row_bounds(b, cyc + dy, qcx + r, qcx + r, st, en);
                    scan_span(st, en, 1, qxf, qyf, s1, d0, d1, d2v, j0, j1, j2);
                }
            }
        }
    }

    // ---- phase B1 (warp-private): lanes 0..23 compute hidden vectors ----
    {
        const int lql = lane / 3;                  // 0..10 (valid < 8)
        const int k   = lane - lql * 3;
        const int srcl = min(lql, 7) * 4;          // group-leader lane
        const int kj0 = __shfl_sync(0xffffffffu, j0, srcl);
        const int kj1 = __shfl_sync(0xffffffffu, j1, srcl);
        const int kj2 = __shfl_sync(0xffffffffu, j2, srcl);
        if (lane < 24) {
            const int idx = (k == 0) ? kj0 : (k == 1) ? kj1 : kj2;
            const float4 p = __ldg(&g_pts[b * NPTS + idx]);
            const int mq  = wib * 8 + lql;
            const float mqx = (float)(X0 + (mq & 31));
            const float mqy = (float)(Y0 + (mq >> 5));
            const float ox = p.x - mqx;
            const float oy = p.y - mqy;
            const float nr = sqrtf(ox * ox + oy * oy);
            float* hp = &s_H[(wib * 24 + lane) * 20];
            #pragma unroll
            for (int j = 0; j < 16; j += 4) {
                float4 hv;
                hv.x = fmaxf(fmaf(s_w1[(j+0)*3], ox, fmaf(s_w1[(j+0)*3+1], oy, fmaf(s_w1[(j+0)*3+2], nr, s_b1[j+0]))), 0.f);
                hv.y = fmaxf(fmaf(s_w1[(j+1)*3], ox, fmaf(s_w1[(j+1)*3+1], oy, fmaf(s_w1[(j+1)*3+2], nr, s_b1[j+1]))), 0.f);
                hv.z = fmaxf(fmaf(s_w1[(j+2)*3], ox, fmaf(s_w1[(j+2)*3+1], oy, fmaf(s_w1[(j+2)*3+2], nr, s_b1[j+2]))), 0.f);
                hv.w = fmaxf(fmaf(s_w1[(j+3)*3], ox, fmaf(s_w1[(j+3)*3+1], oy, fmaf(s_w1[(j+3)*3+2], nr, s_b1[j+3]))), 0.f);
                *reinterpret_cast<float4*>(hp + j) = hv;
            }
        }
    }

    // neighbor feature row pointers, broadcast per query
    const float* fpq[8][3];
    #pragma unroll
    for (int g = 0; g < 8; ++g) {
        const int k0 = __shfl_sync(0xffffffffu, j0, g * 4);
        const int k1 = __shfl_sync(0xffffffffu, j1, g * 4);
        const int k2 = __shfl_sync(0xffffffffu, j2, g * 4);
        fpq[g][0] = g_f3dT + (size_t)(b * NPTS + k0) * C3D;
        fpq[g][1] = g_f3dT + (size_t)(b * NPTS + k1) * C3D;
        fpq[g][2] = g_f3dT + (size_t)(b * NPTS + k2) * C3D;
    }

    float w2r0[16], w2r1[16];
    #pragma unroll
    for (int j = 0; j < 16; ++j) {
        w2r0[j] = w2[lane * 16 + j];
        w2r1[j] = w2[(lane + 32) * 16 + j];
    }
    const float b2a = b2[lane], b2b = b2[lane + 32];
    __syncwarp();   // B1 writes -> B2 reads (warp-private region)

    // ---- phase B2: software-pipelined score + gather ----
    // Prefetch query qq+1's 6 feature values while computing qq's scores.
    float acc0q[8], acc1q[8];
    float pf0[3], pf1[3];
    #pragma unroll
    for (int k = 0; k < 3; ++k) {
        pf0[k] = __ldg(fpq[0][k] + lane);
        pf1[k] = __ldg(fpq[0][k] + lane + 32);
    }
    #pragma unroll
    for (int qq = 0; qq < 8; ++qq) {
        float f0[3], f1[3];
        #pragma unroll
        for (int k = 0; k < 3; ++k) { f0[k] = pf0[k]; f1[k] = pf1[k]; }
        if (qq < 7) {
            #pragma unroll
            for (int k = 0; k < 3; ++k) {
                pf0[k] = __ldg(fpq[qq + 1][k] + lane);
                pf1[k] = __ldg(fpq[qq + 1][k] + lane + 32);
            }
        }
        float a0 = 0.f, a1 = 0.f;
        #pragma unroll
        for (int k = 0; k < KNN; ++k) {
            const float* hp = &s_H[(wib * 24 + qq * 3 + k) * 20];
            const float4 h0 = *reinterpret_cast<const float4*>(hp);
            const float4 h1 = *reinterpret_cast<const float4*>(hp + 4);
            const float4 h2 = *reinterpret_cast<const float4*>(hp + 8);
            const float4 h3 = *reinterpret_cast<const float4*>(hp + 12);
            float e0a = b2a, e0b = 0.f, e1a = b2b, e1b = 0.f;
            e0a = fmaf(w2r0[0],  h0.x, e0a); e1a = fmaf(w2r1[0],  h0.x, e1a);
            e0b = fmaf(w2r0[1],  h0.y, e0b); e1b = fmaf(w2r1[1],  h0.y, e1b);
            e0a = fmaf(w2r0[2],  h0.z, e0a); e1a = fmaf(w2r1[2],  h0.z, e1a);
            e0b = fmaf(w2r0[3],  h0.w, e0b); e1b = fmaf(w2r1[3],  h0.w, e1b);
            e0a = fmaf(w2r0[4],  h1.x, e0a); e1a = fmaf(w2r1[4],  h1.x, e1a);
            e0b = fmaf(w2r0[5],  h1.y, e0b); e1b = fmaf(w2r1[5],  h1.y, e1b);
            e0a = fmaf(w2r0[6],  h1.z, e0a); e1a = fmaf(w2r1[6],  h1.z, e1a);
            e0b = fmaf(w2r0[7],  h1.w, e0b); e1b = fmaf(w2r1[7],  h1.w, e1b);
            e0a = fmaf(w2r0[8],  h2.x, e0a); e1a = fmaf(w2r1[8],  h2.x, e1a);
            e0b = fmaf(w2r0[9],  h2.y, e0b); e1b = fmaf(w2r1[9],  h2.y, e1b);
            e0a = fmaf(w2r0[10], h2.z, e0a); e1a = fmaf(w2r1[10], h2.z, e1a);
            e0b = fmaf(w2r0[11], h2.w, e0b); e1b = fmaf(w2r1[11], h2.w, e1b);
            e0a = fmaf(w2r0[12], h3.x, e0a); e1a = fmaf(w2r1[12], h3.x, e1a);
            e0b = fmaf(w2r0[13], h3.y, e0b); e1b = fmaf(w2r1[13], h3.y, e1b);
            e0a = fmaf(w2r0[14], h3.z, e0a); e1a = fmaf(w2r1[14], h3.z, e1a);
            e0b = fmaf(w2r0[15], h3.w, e0b); e1b = fmaf(w2r1[15], h3.w, e1b);
            const float e0 = e0a + e0b;
            const float e1 = e1a + e1b;
            const float s0  = 1.f / (1.f + __expf(-e0));
            const float s1v = 1.f / (1.f + __expf(-e1));
            a0 = fmaf(s0,  f0[k], a0);
            a1 = fmaf(s1v, f1[k], a1);
        }
        acc0q[qq] = a0;
        acc1q[qq] = a1;
    }
    __syncthreads();   // ALL warps' B2 reads of s_H done before aliased s_fin writes

    {
        float* r0 = &s_fin[lane * 68 + wib * 8];
        float* r1 = &s_fin[(lane + 32) * 68 + wib * 8];
        *reinterpret_cast<float4*>(r0)     = make_float4(acc0q[0], acc0q[1], acc0q[2], acc0q[3]);
        *reinterpret_cast<float4*>(r0 + 4) = make_float4(acc0q[4], acc0q[5], acc0q[6], acc0q[7]);
        *reinterpret_cast<float4*>(r1)     = make_float4(acc1q[0], acc1q[1], acc1q[2], acc1q[3]);
        *reinterpret_cast<float4*>(r1 + 4) = make_float4(acc1q[4], acc1q[5], acc1q[6], acc1q[7]);
    }
    __syncthreads();

    // ---- phase C: w3 block GEMM, 4x4 register tile per thread ----
    {
        const int tx_ = t & 15;
        const int ty_ = t >> 4;
        const int o0 = ty_ * 4;
        const int q4 = tx_ * 4;            // stays within one 32-query row
        float r00[4], r01[4], r02[4], r03[4];
        const float bz0 = __ldg(b3 + o0 + 0);
        const float bz1 = __ldg(b3 + o0 + 1);
        const float bz2 = __ldg(b3 + o0 + 2);
        const float bz3 = __ldg(b3 + o0 + 3);
        #pragma unroll
        for (int k = 0; k < 4; ++k) { r00[k] = bz0; r01[k] = bz1; r02[k] = bz2; r03[k] = bz3; }

        #pragma unroll 4
        for (int j = 0; j < 64; ++j) {
            const float4 wv = *reinterpret_cast<const float4*>(&s_w3[j * 68 + o0]);
            const float4 fv = *reinterpret_cast<const float4*>(&s_fin[j * 68 + q4]);
            r00[0] = fmaf(wv.x, fv.x, r00[0]); r00[1] = fmaf(wv.x, fv.y, r00[1]);
            r00[2] = fmaf(wv.x, fv.z, r00[2]); r00[3] = fmaf(wv.x, fv.w, r00[3]);
            r01[0] = fmaf(wv.y, fv.x, r01[0]); r01[1] = fmaf(wv.y, fv.y, r01[1]);
            r01[2] = fmaf(wv.y, fv.z, r01[2]); r01[3] = fmaf(wv.y, fv.w, r01[3]);
            r02[0] = fmaf(wv.z, fv.x, r02[0]); r02[1] = fmaf(wv.z, fv.y, r02[1]);
            r02[2] = fmaf(wv.z, fv.z, r02[2]); r02[3] = fmaf(wv.z, fv.w, r02[3]);
            r03[0] = fmaf(wv.w, fv.x, r03[0]); r03[1] = fmaf(wv.w, fv.y, r03[1]);
            r03[2] = fmaf(wv.w, fv.z, r03[2]); r03[3] = fmaf(wv.w, fv.w, r03[3]);
        }
        const int qy_row = Y0 + (q4 >> 5);
        const int qx0    = X0 + (q4 & 31);
        float* op = out + (size_t)(b * 64 + o0) * HW + qy_row * WW + qx0;
        *reinterpret_cast<float4*>(op) =
            make_float4(fmaxf(r00[0],0.f), fmaxf(r00[1],0.f), fmaxf(r00[2],0.f), fmaxf(r00[3],0.f));
        *reinterpret_cast<float4*>(op + HW) =
            make_float4(fmaxf(r01[0],0.f), fmaxf(r01[1],0.f), fmaxf(r01[2],0.f), fmaxf(r01[3],0.f));
        *reinterpret_cast<float4*>(op + 2 * HW) =
            make_float4(fmaxf(r02[0],0.f), fmaxf(r02[1],0.f), fmaxf(r02[2],0.f), fmaxf(r02[3],0.f));
        *reinterpret_cast<float4*>(op + 3 * HW) =
            make_float4(fmaxf(r03[0],0.f), fmaxf(r03[1],0.f), fmaxf(r03[2],0.f), fmaxf(r03[3],0.f));
    }
}

// ---------------- launch ----------------
extern "C" void kernel_launch(void* const* d_in, const int* in_sizes, int n_in,
                              void* d_out, int out_size) {
    const float* uv  = (const float*)d_in[0];
    // d_in[1] = feat_2d : unused by the reference computation
    const float* f3d = (const float*)d_in[2];
    const float* w1  = (const float*)d_in[3];
    const float* b1  = (const float*)d_in[4];
    const float* w2  = (const float*)d_in[5];
    const float* b2  = (const float*)d_in[6];
    const float* w3  = (const float*)d_in[7];
    const float* b3  = (const float*)d_in[8];
    float* out = (float*)d_out;

    prep_kernel<<<1024 + 64, 256>>>(uv, f3d);
    scan_kernel<<<1, 1024>>>();
    scatter_kernel<<<64, 256>>>();
    fused_kernel<<<dim3(WW / 32, HH / 2, BS), 256>>>(w1, b1, w2, b2, w3, b3, out);
}

// round 16
// speedup vs baseline: 1.1832x; 1.1832x over previous
#include <cuda_runtime.h>
#include <math.h>

#define BS 2
#define NPTS 8192
#define C3D 64
#define HH 64
#define WW 160
#define HW (HH*WW)
#define KNN 3

#define CW 80          // cells in x (2px each)
#define CHC 32         // cells in y
#define NCELL (CW*CHC)
#define NTOT (BS*NCELL)

#define NCAND 576      // smem candidate cap (expected ~320 for 5 rows)

#define FLT_BIG 3.402823466e+38f

// ---------------- scratch ----------------
__device__ float4 g_pts[BS * NPTS];        // (x, y, s2_replica, 0) by original index
__device__ int    g_cnt[NTOT];             // zero-init; re-zeroed by fused kernel each run
__device__ int    g_rowstart[NTOT + 1];
__device__ int    g_off[NTOT];
__device__ float4 g_cpts[BS * NPTS];       // CSR-compacted (x, y, s2, idx_bits)
__device__ float  g_f3dT[BS * NPTS * C3D]; // point-major feat_3d

__device__ __forceinline__ int cell_of(float ux, float uy, int b) {
    int cx = (int)(ux * 0.5f); cx = max(0, min(CW - 1, cx));
    int cy = (int)(uy * 0.5f); cy = max(0, min(CHC - 1, cy));
    return (b * CHC + cy) * CW + cx;
}

// ---------------- K1: transpose feat_3d (vectorized) + pack/count ----------
__global__ void __launch_bounds__(256) prep_kernel(const float* __restrict__ uv,
                                                   const float* __restrict__ f3d) {
    const int t = threadIdx.x;
    if (blockIdx.x < 1024) {
        __shared__ float tile[32][33];
        const int bid = blockIdx.x;
        const int b  = bid >> 9;
        const int c0 = ((bid >> 8) & 1) * 32;
        const int n0 = (bid & 255) * 32;
        const int tx2 = t & 7;
        const int row = t >> 3;
        float4 v = *reinterpret_cast<const float4*>(
            f3d + ((size_t)(b * C3D + c0 + row)) * NPTS + n0 + tx2 * 4);
        tile[row][tx2 * 4 + 0] = v.x;
        tile[row][tx2 * 4 + 1] = v.y;
        tile[row][tx2 * 4 + 2] = v.z;
        tile[row][tx2 * 4 + 3] = v.w;
        __syncthreads();
        const int n = t >> 3;
        float4 o;
        o.x = tile[tx2 * 4 + 0][n];
        o.y = tile[tx2 * 4 + 1][n];
        o.z = tile[tx2 * 4 + 2][n];
        o.w = tile[tx2 * 4 + 3][n];
        *reinterpret_cast<float4*>(
            g_f3dT + ((size_t)(b * NPTS + n0 + n)) * C3D + c0 + tx2 * 4) = o;
    } else {
        const int i = (blockIdx.x - 1024) * 256 + t;
        const int b = i >> 13;
        const int n = i & (NPTS - 1);
        const float ux = uv[(b * 2 + 0) * NPTS + n];
        const float uy = uv[(b * 2 + 1) * NPTS + n];
        const float s2 = __fadd_rn(__fmul_rn(ux, ux), __fmul_rn(uy, uy));
        g_pts[i] = make_float4(ux, uy, s2, 0.0f);
        atomicAdd(&g_cnt[cell_of(ux, uy, b)], 1);
    }
}

// ---------------- K2: exclusive scan over NTOT=5120 cells (one block) ----------
__global__ void __launch_bounds__(1024) scan_kernel() {
    const int t = threadIdx.x;
    int c[5], s = 0;
    #pragma unroll
    for (int k = 0; k < 5; ++k) { c[k] = g_cnt[t * 5 + k]; s += c[k]; }
    const int lane = t & 31, w = t >> 5;
    int v = s;
    #pragma unroll
    for (int o = 1; o < 32; o <<= 1) {
        int u = __shfl_up_sync(0xffffffffu, v, o);
        if (lane >= o) v += u;
    }
    __shared__ int ws[32];
    if (lane == 31) ws[w] = v;
    __syncthreads();
    if (w == 0) {
        int x = ws[lane];
        #pragma unroll
        for (int o = 1; o < 32; o <<= 1) {
            int u = __shfl_up_sync(0xffffffffu, x, o);
            if (lane >= o) x += u;
        }
        ws[lane] = x;
    }
    __syncthreads();
    int run = v - s + (w > 0 ? ws[w - 1] : 0);
    #pragma unroll
    for (int k = 0; k < 5; ++k) {
        g_rowstart[t * 5 + k] = run;
        g_off[t * 5 + k] = run;
        run += c[k];
    }
    if (t == 1023) g_rowstart[NTOT] = run;
}

// ---------------- K3: scatter into CSR ----------------
__global__ void __launch_bounds__(256) scatter_kernel() {
    const int i = blockIdx.x * 256 + threadIdx.x;
    const int b = i >> 13;
    const int n = i & (NPTS - 1);
    const float4 p = g_pts[i];
    const int slot = atomicAdd(&g_off[cell_of(p.x, p.y, b)], 1);
    g_cpts[slot] = make_float4(p.x, p.y, p.z, __int_as_float(n));
}

// ---------------- helpers ----------------
__device__ __forceinline__ bool lessMI(float ma, int ia, float mb, int ib) {
    return (ma < mb) || (ma == mb && ia < ib);
}
__device__ __forceinline__ void ins(float d, int id,
                                    float& d0, float& d1, float& d2v,
                                    int& j0, int& j1, int& j2) {
    if (lessMI(d, id, d2v, j2)) {
        if (lessMI(d, id, d1, j1)) {
            d2v = d1; j2 = j1;
            if (lessMI(d, id, d0, j0)) { d1 = d0; j1 = j0; d0 = d; j0 = id; }
            else                       { d1 = d;  j1 = id; }
        } else { d2v = d; j2 = id; }
    }
}
// Dedup insert for merges: skips (d,id) already present (ids are unique per point).
__device__ __forceinline__ void ins_dedup(float d, int id,
                                          float& d0, float& d1, float& d2v,
                                          int& j0, int& j1, int& j2) {
    if (id == j0 || id == j1 || id == j2) return;
    ins(d, id, d0, d1, d2v, j0, j1, j2);
}
__device__ __forceinline__ void eval_pt(const float4 p, float qxf, float qyf, float s1,
                                        float& d0, float& d1, float& d2v,
                                        int& j0, int& j1, int& j2) {
    const float dot = __fmaf_rn(qyf, p.y, __fmul_rn(qxf, p.x));
    const float d2  = __fsub_rn(__fadd_rn(s1, p.z), __fmul_rn(2.0f, dot));
    ins(d2, __float_as_int(p.w), d0, d1, d2v, j0, j1, j2);
}
__device__ __forceinline__ void scan_span(int st, int en, int stride,
                                          float qxf, float qyf, float s1,
                                          float& d0, float& d1, float& d2v,
                                          int& j0, int& j1, int& j2) {
    for (int s = st; s < en; s += stride)
        eval_pt(__ldg(&g_cpts[s]), qxf, qyf, s1, d0, d1, d2v, j0, j1, j2);
}
__device__ __forceinline__ void row_bounds(int b, int cy, int cxlo, int cxhi,
                                           int& st, int& en) {
    st = 0; en = 0;
    if (cy < 0 || cy >= CHC) return;
    cxlo = max(cxlo, 0); cxhi = min(cxhi, CW - 1);
    if (cxlo > cxhi) return;
    const int rowbase = (b * CHC + cy) * CW;
    st = g_rowstart[rowbase + cxlo];
    en = g_rowstart[rowbase + cxhi + 1];
}

// ---------------- K4: fused, warp-private A->B1->B2, GEMM C ----------
// block = 32x2 pixel tile (64 queries), 256 threads, 3 blocks/SM -> one wave.
__global__ void __launch_bounds__(256, 3) fused_kernel(
    const float* __restrict__ w1, const float* __restrict__ b1,
    const float* __restrict__ w2, const float* __restrict__ b2,
    const float* __restrict__ w3, const float* __restrict__ b3,
    float* __restrict__ out) {

    __shared__ float  s_w3[64 * 68];   // [j*68 + o] = w3[o][j]
    __shared__ float  s_buf[64 * 68];  // union: s_H (warp-private) then s_fin [j*68+lq]
    __shared__ float4 s_cand[NCAND];   // staged candidate points (5 cell rows)
    __shared__ int    s_rs[5][21];     // absolute rowstart boundaries per cell-row
    __shared__ int    s_st[5], s_cnt[5];
    __shared__ float  s_w1[48];
    __shared__ float  s_b1[16];

    float* const s_H   = s_buf;        // [ (wib*24 + l) * 20 + j ], l = 0..23
    float* const s_fin = s_buf;        // [ j*68 + lq ], live after all B2 reads

    const int t    = threadIdx.x;
    const int lane = t & 31;
    const int wib  = t >> 5;
    const int b    = blockIdx.z;
    const int X0   = blockIdx.x * 32;
    const int Y0   = blockIdx.y * 2;

    const int cyc  = Y0 >> 1;
    const int cxlo = max(X0 / 2 - 2, 0);
    const int cxhi = min(X0 / 2 + 17, CW - 1);

    // reset cell counters for next invocation (consumed earlier this run by scan)
    const int gtid = ((blockIdx.z * gridDim.y + blockIdx.y) * gridDim.x + blockIdx.x) * 256 + t;
    if (gtid < NTOT) g_cnt[gtid] = 0;

    if (t < 48) s_w1[t] = w1[t];
    if (t < 16) s_b1[t] = b1[t];

    // row bounds + boundary table for 5 cell rows (cyc-2 .. cyc+2)
    if (t < 5) {
        const int row = cyc - 2 + t;
        int st = 0, en = 0;
        if (row >= 0 && row < CHC) {
            const int rowbase = (b * CHC + row) * CW;
            st = g_rowstart[rowbase + cxlo];
            en = g_rowstart[rowbase + cxhi + 1];
        }
        s_st[t] = st; s_cnt[t] = en - st;
    }
    if (t < 105) {
        const int r = t / 21, c = t % 21;
        const int row = cyc - 2 + r;
        if (row >= 0 && row < CHC && c <= cxhi + 1 - cxlo)
            s_rs[r][c] = g_rowstart[(b * CHC + row) * CW + cxlo + c];
    }
    __syncthreads();

    int base_[5];
    base_[0] = 0;
    #pragma unroll
    for (int r = 1; r < 5; ++r) base_[r] = base_[r - 1] + s_cnt[r - 1];
    const int total_cand = base_[4] + s_cnt[4];
    const bool ovf = total_cand > NCAND;

    if (!ovf) {
        #pragma unroll
        for (int r = 0; r < 5; ++r) {
            const int cr = s_cnt[r], sr = s_st[r], br = base_[r];
            for (int i = t; i < cr; i += 256) s_cand[br + i] = __ldg(&g_cpts[sr + i]);
        }
    }

    // stage w3 transposed (coalesced gmem reads) — overlaps candidate copy
    for (int e = t; e < 64 * 64; e += 256) {
        int o = e >> 6, j = e & 63;
        s_w3[j * 68 + o] = w3[e];
    }
    __syncthreads();

    // ---- phase A: knn, 4 lanes per query, 3x3 fast path from smem ----
    const int sub = lane & 3;
    const int qq0 = lane >> 2;               // 0..7
    const int lq  = wib * 8 + qq0;           // 0..63
    const int qx  = X0 + (lq & 31);
    const int qy  = Y0 + (lq >> 5);
    const float qxf = (float)qx;
    const float qyf = (float)qy;
    const float s1  = __fadd_rn(__fmul_rn(qxf, qxf), __fmul_rn(qyf, qyf));
    const int qcx = qx >> 1;

    float d0 = FLT_BIG, d1 = FLT_BIG, d2v = FLT_BIG;
    int   j0 = 0x7fffffff, j1 = 0x7fffffff, j2 = 0x7fffffff;

    auto scan_cells_smem = [&](int ri, int clo, int chi) {
        const int row = cyc - 2 + ri;
        if (row < 0 || row >= CHC) return;
        clo = max(clo, cxlo); chi = min(chi, cxhi);
        if (clo > chi) return;
        const int lo_i = clo - cxlo, hi_i = chi - cxlo;
        const int ss = s_rs[ri][lo_i]     - s_st[ri] + base_[ri];
        const int ee = s_rs[ri][hi_i + 1] - s_st[ri] + base_[ri];
        for (int s = ss + sub; s < ee; s += 4)
            eval_pt(s_cand[s], qxf, qyf, s1, d0, d1, d2v, j0, j1, j2);
    };
    auto merge4 = [&]() {
        #pragma unroll
        for (int m = 1; m <= 2; m <<= 1) {
            float od0 = __shfl_xor_sync(0xffffffffu, d0,  m);
            float od1 = __shfl_xor_sync(0xffffffffu, d1,  m);
            float od2 = __shfl_xor_sync(0xffffffffu, d2v, m);
            int   oj0 = __shfl_xor_sync(0xffffffffu, j0,  m);
            int   oj1 = __shfl_xor_sync(0xffffffffu, j1,  m);
            int   oj2 = __shfl_xor_sync(0xffffffffu, j2,  m);
            ins_dedup(od0, oj0, d0, d1, d2v, j0, j1, j2);
            ins_dedup(od1, oj1, d0, d1, d2v, j0, j1, j2);
            ins_dedup(od2, oj2, d0, d1, d2v, j0, j1, j2);
        }
    };

    if (!ovf) {
        #pragma unroll
        for (int ri = 1; ri <= 3; ++ri)
            scan_cells_smem(ri, qcx - 1, qcx + 1);
        merge4();
        {
            const bool need = (d2v + 0.5f >= 4.0f);
            if (__any_sync(0xffffffffu, need)) {
                if (need) {
                    scan_cells_smem(0, qcx - 2, qcx + 2);
                    scan_cells_smem(4, qcx - 2, qcx + 2);
                    #pragma unroll
                    for (int ri = 1; ri <= 3; ++ri) {
                        scan_cells_smem(ri, qcx - 2, qcx - 2);
                        scan_cells_smem(ri, qcx + 2, qcx + 2);
                    }
                }
                merge4();
            }
        }
        if (sub == 0 && d2v + 0.5f >= 16.0f) {
            // tier-2 (P ~ 1e-14): exact serial gmem rings beyond the 5x5
            for (int r = 3; r < 96; ++r) {
                const float lb = 2.0f * (float)(r - 1);
                if (lb * lb > d2v + 0.5f) break;
                int st, en;
                row_bounds(b, cyc - r, qcx - r, qcx + r, st, en);
                scan_span(st, en, 1, qxf, qyf, s1, d0, d1, d2v, j0, j1, j2);
                row_bounds(b, cyc + r, qcx - r, qcx + r, st, en);
                scan_span(st, en, 1, qxf, qyf, s1, d0, d1, d2v, j0, j1, j2);
                for (int dy = -r + 1; dy <= r - 1; ++dy) {
                    row_bounds(b, cyc + dy, qcx - r, qcx - r, st, en);
                    scan_span(st, en, 1, qxf, qyf, s1, d0, d1, d2v, j0, j1, j2);
                    row_bounds(b, cyc + dy, qcx + r, qcx + r, st, en);
                    scan_span(st, en, 1, qxf, qyf, s1, d0, d1, d2v, j0, j1, j2);
                }
            }
        }
    } else {
        // overflow path (statistically never): same candidate sets from gmem
        #pragma unroll
        for (int dy = -1; dy <= 1; ++dy) {
            int st, en;
            row_bounds(b, cyc + dy, qcx - 1, qcx + 1, st, en);
            scan_span(st + sub, en, 4, qxf, qyf, s1, d0, d1, d2v, j0, j1, j2);
        }
        merge4();
        if (sub == 0 && d2v + 0.5f >= 4.0f) {
            for (int r = 2; r < 96; ++r) {
                const float lb = 2.0f * (float)(r - 1);
                if (lb * lb > d2v + 0.5f) break;
                int st, en;
                row_bounds(b, cyc - r, qcx - r, qcx + r, st, en);
                scan_span(st, en, 1, qxf, qyf, s1, d0, d1, d2v, j0, j1, j2);
                row_bounds(b, cyc + r, qcx - r, qcx + r, st, en);
                scan_span(st, en, 1, qxf, qyf, s1, d0, d1, d2v, j0, j1, j2);
                for (int dy = -r + 1; dy <= r - 1; ++dy) {
                    row_bounds(b, cyc + dy, qcx - r, qcx - r, st, en);
                    scan_span(st, en, 1, qxf, qyf, s1, d0, d1, d2v, j0, j1, j2);
                    row_bounds(b, cyc + dy, qcx + r, qcx + r, st, en);
                    scan_span(st, en, 1, qxf, qyf, s1, d0, d1, d2v, j0, j1, j2);
                }
            }
        }
    }

    // ---- phase B1 (warp-private): lanes 0..23 compute hidden vectors ----
    {
        const int lql = lane / 3;                  // 0..10 (valid < 8)
        const int k   = lane - lql * 3;
        const int srcl = min(lql, 7) * 4;          // group-leader lane
        const int kj0 = __shfl_sync(0xffffffffu, j0, srcl);
        const int kj1 = __shfl_sync(0xffffffffu, j1, srcl);
        const int kj2 = __shfl_sync(0xffffffffu, j2, srcl);
        if (lane < 24) {
            const int idx = (k == 0) ? kj0 : (k == 1) ? kj1 : kj2;
            const float4 p = __ldg(&g_pts[b * NPTS + idx]);
            const int mq  = wib * 8 + lql;
            const float mqx = (float)(X0 + (mq & 31));
            const float mqy = (float)(Y0 + (mq >> 5));
            const float ox = p.x - mqx;
            const float oy = p.y - mqy;
            const float nr = sqrtf(ox * ox + oy * oy);
            float* hp = &s_H[(wib * 24 + lane) * 20];
            #pragma unroll
            for (int j = 0; j < 16; j += 4) {
                float4 hv;
                hv.x = fmaxf(fmaf(s_w1[(j+0)*3], ox, fmaf(s_w1[(j+0)*3+1], oy, fmaf(s_w1[(j+0)*3+2], nr, s_b1[j+0]))), 0.f);
                hv.y = fmaxf(fmaf(s_w1[(j+1)*3], ox, fmaf(s_w1[(j+1)*3+1], oy, fmaf(s_w1[(j+1)*3+2], nr, s_b1[j+1]))), 0.f);
                hv.z = fmaxf(fmaf(s_w1[(j+2)*3], ox, fmaf(s_w1[(j+2)*3+1], oy, fmaf(s_w1[(j+2)*3+2], nr, s_b1[j+2]))), 0.f);
                hv.w = fmaxf(fmaf(s_w1[(j+3)*3], ox, fmaf(s_w1[(j+3)*3+1], oy, fmaf(s_w1[(j+3)*3+2], nr, s_b1[j+3]))), 0.f);
                *reinterpret_cast<float4*>(hp + j) = hv;
            }
        }
    }

    // neighbor indices for B2, broadcast to the whole warp per query
    int knn_q[8][3];
    #pragma unroll
    for (int g = 0; g < 8; ++g) {
        knn_q[g][0] = __shfl_sync(0xffffffffu, j0, g * 4);
        knn_q[g][1] = __shfl_sync(0xffffffffu, j1, g * 4);
        knn_q[g][2] = __shfl_sync(0xffffffffu, j2, g * 4);
    }

    float w2r0[16], w2r1[16];
    #pragma unroll
    for (int j = 0; j < 16; ++j) {
        w2r0[j] = w2[lane * 16 + j];
        w2r1[j] = w2[(lane + 32) * 16 + j];
    }
    const float b2a = b2[lane], b2b = b2[lane + 32];
    __syncwarp();   // B1 writes -> B2 reads (warp-private region)

    // ---- phase B2: score + gather (warp = 8 queries, lane = 2 channels) ----
    float acc0q[8], acc1q[8];
    #pragma unroll
    for (int qq = 0; qq < 8; ++qq) {
        float a0 = 0.f, a1 = 0.f;
        #pragma unroll
        for (int k = 0; k < KNN; ++k) {
            const int idx = knn_q[qq][k];
            const float* hp = &s_H[(wib * 24 + qq * 3 + k) * 20];
            const float4 h0 = *reinterpret_cast<const float4*>(hp);
            const float4 h1 = *reinterpret_cast<const float4*>(hp + 4);
            const float4 h2 = *reinterpret_cast<const float4*>(hp + 8);
            const float4 h3 = *reinterpret_cast<const float4*>(hp + 12);
            // dual accumulators halve the dependency chain
            float e0a = b2a, e0b = 0.f, e1a = b2b, e1b = 0.f;
            e0a = fmaf(w2r0[0],  h0.x, e0a); e1a = fmaf(w2r1[0],  h0.x, e1a);
            e0b = fmaf(w2r0[1],  h0.y, e0b); e1b = fmaf(w2r1[1],  h0.y, e1b);
            e0a = fmaf(w2r0[2],  h0.z, e0a); e1a = fmaf(w2r1[2],  h0.z, e1a);
            e0b = fmaf(w2r0[3],  h0.w, e0b); e1b = fmaf(w2r1[3],  h0.w, e1b);
            e0a = fmaf(w2r0[4],  h1.x, e0a); e1a = fmaf(w2r1[4],  h1.x, e1a);
            e0b = fmaf(w2r0[5],  h1.y, e0b); e1b = fmaf(w2r1[5],  h1.y, e1b);
            e0a = fmaf(w2r0[6],  h1.z, e0a); e1a = fmaf(w2r1[6],  h1.z, e1a);
            e0b = fmaf(w2r0[7],  h1.w, e0b); e1b = fmaf(w2r1[7],  h1.w, e1b);
            e0a = fmaf(w2r0[8],  h2.x, e0a); e1a = fmaf(w2r1[8],  h2.x, e1a);
            e0b = fmaf(w2r0[9],  h2.y, e0b); e1b = fmaf(w2r1[9],  h2.y, e1b);
            e0a = fmaf(w2r0[10], h2.z, e0a); e1a = fmaf(w2r1[10], h2.z, e1a);
            e0b = fmaf(w2r0[11], h2.w, e0b); e1b = fmaf(w2r1[11], h2.w, e1b);
            e0a = fmaf(w2r0[12], h3.x, e0a); e1a = fmaf(w2r1[12], h3.x, e1a);
            e0b = fmaf(w2r0[13], h3.y, e0b); e1b = fmaf(w2r1[13], h3.y, e1b);
            e0a = fmaf(w2r0[14], h3.z, e0a); e1a = fmaf(w2r1[14], h3.z, e1a);
            e0b = fmaf(w2r0[15], h3.w, e0b); e1b = fmaf(w2r1[15], h3.w, e1b);
            const float e0 = e0a + e0b;
            const float e1 = e1a + e1b;
            const float s0  = 1.f / (1.f + __expf(-e0));
            const float s1v = 1.f / (1.f + __expf(-e1));
            const float* fp = g_f3dT + (size_t)(b * NPTS + idx) * C3D;
            a0 = fmaf(s0,  __ldg(fp + lane),      a0);
            a1 = fmaf(s1v, __ldg(fp + lane + 32), a1);
        }
        acc0q[qq] = a0;
        acc1q[qq] = a1;
    }
    __syncthreads();   // ALL warps' B2 reads of s_H done before aliased s_fin writes

    {
        float* r0 = &s_fin[lane * 68 + wib * 8];
        float* r1 = &s_fin[(lane + 32) * 68 + wib * 8];
        *reinterpret_cast<float4*>(r0)     = make_float4(acc0q[0], acc0q[1], acc0q[2], acc0q[3]);
        *reinterpret_cast<float4*>(r0 + 4) = make_float4(acc0q[4], acc0q[5], acc0q[6], acc0q[7]);
        *reinterpret_cast<float4*>(r1)     = make_float4(acc1q[0], acc1q[1], acc1q[2], acc1q[3]);
        *reinterpret_cast<float4*>(r1 + 4) = make_float4(acc1q[4], acc1q[5], acc1q[6], acc1q[7]);
    }
    __syncthreads();

    // ---- phase C: w3 block GEMM, 4x4 register tile per thread ----
    {
        const int tx_ = t & 15;
        const int ty_ = t >> 4;
        const int o0 = ty_ * 4;
        const int q4 = tx_ * 4;            // stays within one 32-query row
        float r00[4], r01[4], r02[4], r03[4];
        const float bz0 = __ldg(b3 + o0 + 0);
        const float bz1 = __ldg(b3 + o0 + 1);
        const float bz2 = __ldg(b3 + o0 + 2);
        const float bz3 = __ldg(b3 + o0 + 3);
        #pragma unroll
        for (int k = 0; k < 4; ++k) { r00[k] = bz0; r01[k] = bz1; r02[k] = bz2; r03[k] = bz3; }

        #pragma unroll 4
        for (int j = 0; j < 64; ++j) {
            const float4 wv = *reinterpret_cast<const float4*>(&s_w3[j * 68 + o0]);
            const float4 fv = *reinterpret_cast<const float4*>(&s_fin[j * 68 + q4]);
            r00[0] = fmaf(wv.x, fv.x, r00[0]); r00[1] = fmaf(wv.x, fv.y, r00[1]);
            r00[2] = fmaf(wv.x, fv.z, r00[2]); r00[3] = fmaf(wv.x, fv.w, r00[3]);
            r01[0] = fmaf(wv.y, fv.x, r01[0]); r01[1] = fmaf(wv.y, fv.y, r01[1]);
            r01[2] = fmaf(wv.y, fv.z, r01[2]); r01[3] = fmaf(wv.y, fv.w, r01[3]);
            r02[0] = fmaf(wv.z, fv.x, r02[0]); r02[1] = fmaf(wv.z, fv.y, r02[1]);
            r02[2] = fmaf(wv.z, fv.z, r02[2]); r02[3] = fmaf(wv.z, fv.w, r02[3]);
            r03[0] = fmaf(wv.w, fv.x, r03[0]); r03[1] = fmaf(wv.w, fv.y, r03[1]);
            r03[2] = fmaf(wv.w, fv.z, r03[2]); r03[3] = fmaf(wv.w, fv.w, r03[3]);
        }
        const int qy_row = Y0 + (q4 >> 5);
        const int qx0    = X0 + (q4 & 31);
        float* op = out + (size_t)(b * 64 + o0) * HW + qy_row * WW + qx0;
        *reinterpret_cast<float4*>(op) =
            make_float4(fmaxf(r00[0],0.f), fmaxf(r00[1],0.f), fmaxf(r00[2],0.f), fmaxf(r00[3],0.f));
        *reinterpret_cast<float4*>(op + HW) =
            make_float4(fmaxf(r01[0],0.f), fmaxf(r01[1],0.f), fmaxf(r01[2],0.f), fmaxf(r01[3],0.f));
        *reinterpret_cast<float4*>(op + 2 * HW) =
            make_float4(fmaxf(r02[0],0.f), fmaxf(r02[1],0.f), fmaxf(r02[2],0.f), fmaxf(r02[3],0.f));
        *reinterpret_cast<float4*>(op + 3 * HW) =
            make_float4(fmaxf(r03[0],0.f), fmaxf(r03[1],0.f), fmaxf(r03[2],0.f), fmaxf(r03[3],0.f));
    }
}

// ---------------- launch ----------------
extern "C" void kernel_launch(void* const* d_in, const int* in_sizes, int n_in,
                              void* d_out, int out_size) {
    const float* uv  = (const float*)d_in[0];
    // d_in[1] = feat_2d : unused by the reference computation
    const float* f3d = (const float*)d_in[2];
    const float* w1  = (const float*)d_in[3];
    const float* b1  = (const float*)d_in[4];
    const float* w2  = (const float*)d_in[5];
    const float* b2  = (const float*)d_in[6];
    const float* w3  = (const float*)d_in[7];
    const float* b3  = (const float*)d_in[8];
    float* out = (float*)d_out;

    prep_kernel<<<1024 + 64, 256>>>(uv, f3d);
    scan_kernel<<<1, 1024>>>();
    scatter_kernel<<<64, 256>>>();
    fused_kernel<<<dim3(WW / 32, HH / 2, BS), 256>>>(w1, b1, w2, b2, w3, b3, out);
}